// round 13
// baseline (speedup 1.0000x reference)
#include <cuda_runtime.h>
#include <math.h>

// Shapes fixed by the problem: T=3, B=4, N=4096, K=8.
constexpr int TT = 3;
constexpr int BB = 4;
constexpr int NN = 4096;
constexpr int KK = 8;
constexpr int TOT = BB * NN;               // 16384 rows
constexpr int NB_CHUNKS = 8;
constexpr int NB_COLS = NN / NB_CHUNKS;    // 512
constexpr int NB_K = 9;                    // top-9 (self dropped in merge)
constexpr int NPAIR = NN / 2;              // 2048 packed column pairs per set
constexpr int CCH = 4;                     // chamfer column chunks
constexpr int CPAIR = NPAIR / CCH;         // 512 pairs per chamfer chunk
constexpr int CH_BLOCKS = 24 * CCH * 4;    // 384 chamfer blocks (96 jobs x 4)
constexpr int NB_BLOCKS = 256;             // 32 row-blocks x 8 chunks, 2 rows/thread
constexpr int FUSED_BLOCKS = CH_BLOCKS + NB_BLOCKS; // 640 = 128 * 5

// Partial-sum slot layout (deterministic reduction — no float atomics)
constexpr int P_CH   = 0;                  // 24 problems * 16 blocks = 384
constexpr int P_PD   = 384;                // 64
constexpr int P_SP   = 448;                // 64
constexpr int P_TRAN = 512;                // 1
constexpr int P_ARAP = 513;                // 3 * 64 = 192
constexpr int NPART  = 705;

// Scratch (device globals — no allocations allowed)
__device__ ulonglong2 g_tgtA[BB * NPAIR];      // (-2x pair, -2y pair) target
__device__ ulonglong2 g_tgtB[BB * NPAIR];      // (-2z pair, |p|^2 pair)
__device__ ulonglong2 g_dpA[TT * BB * NPAIR];  // same for deformation pts
__device__ ulonglong2 g_dpB[TT * BB * NPAIR];
__device__ float4 g_cols_src[TOT];             // (-2x,-2y,-2z,|x|^2) src (kNN)
__device__ float4 g_dp4[TT * TOT];             // raw dp coords (arap gathers)
__device__ unsigned int g_nb[NB_CHUNKS * NB_K * TOT];  // packed keys [chunk][k][m]
__device__ int    g_idx[KK * TOT];             // [k][m]
__device__ float  g_sd[KK * TOT];
__device__ float  g_cmin[24 * CCH * NN];       // chamfer partial row-mins
__device__ float  g_partial[NPART];

// ---------------------------------------------------------------------------
__device__ __forceinline__ unsigned long long packf2(float a, float b) {
    unsigned long long r;
    asm("mov.b64 %0, {%1, %2};" : "=l"(r) : "f"(a), "f"(b));
    return r;
}
__device__ __forceinline__ void unpackf2(float& a, float& b, unsigned long long v) {
    asm("mov.b64 {%0, %1}, %2;" : "=f"(a), "=f"(b) : "l"(v));
}
__device__ __forceinline__ unsigned long long fma2(unsigned long long a,
                                                   unsigned long long b,
                                                   unsigned long long c) {
    unsigned long long d;
    asm("fma.rn.f32x2 %0, %1, %2, %3;" : "=l"(d) : "l"(a), "l"(b), "l"(c));
    return d;
}

template <int BS>
__device__ __forceinline__ float block_reduce_sum(float v, float* sh) {
    int tid = threadIdx.x;
    sh[tid] = v;
    __syncthreads();
    #pragma unroll
    for (int s = BS / 2; s > 0; s >>= 1) {
        if (tid < s) sh[tid] += sh[tid + s];
        __syncthreads();
    }
    float r = sh[0];
    __syncthreads();
    return r;
}

// Merge a sorted key pair (lo <= hi) into the sorted top-9 bd[] via DPX
// vimin3; evaluated descending so old slot values are consumed first.
__device__ __forceinline__ void merge_pair9(unsigned int (&bd)[NB_K],
                                            unsigned int lo, unsigned int hi) {
    #pragma unroll
    for (int s = NB_K - 1; s >= 2; --s)
        bd[s] = __vimin3_u32(bd[s], max(bd[s - 1], lo), max(bd[s - 2], hi));
    bd[1] = __vimin3_u32(bd[1], max(bd[0], lo), hi);
    bd[0] = min(bd[0], lo);
}

// ---------------------------------------------------------------------------
// prepA: packed f32x2 chamfer columns for target + dp, and raw dp4 coords.
__global__ void prepA_kernel(const float* __restrict__ tgt,
                             const float* __restrict__ dpt) {
    int i = blockIdx.x * 256 + threadIdx.x;   // 0 .. 32767
    if (i < BB * NPAIR) {                     // target pairs
        const float* p = tgt + (size_t)i * 6;
        float x0 = p[0], y0 = p[1], z0 = p[2];
        float x1 = p[3], y1 = p[4], z1 = p[5];
        float w0 = fmaf(x0, x0, fmaf(y0, y0, z0 * z0));
        float w1 = fmaf(x1, x1, fmaf(y1, y1, z1 * z1));
        g_tgtA[i] = make_ulonglong2(packf2(-2.f * x0, -2.f * x1),
                                    packf2(-2.f * y0, -2.f * y1));
        g_tgtB[i] = make_ulonglong2(packf2(-2.f * z0, -2.f * z1),
                                    packf2(w0, w1));
    } else {                                  // dp pairs (+ raw dp4)
        int j = i - BB * NPAIR;
        if (j >= TT * BB * NPAIR) return;
        const float* p = dpt + (size_t)j * 6;
        float x0 = p[0], y0 = p[1], z0 = p[2];
        float x1 = p[3], y1 = p[4], z1 = p[5];
        float w0 = fmaf(x0, x0, fmaf(y0, y0, z0 * z0));
        float w1 = fmaf(x1, x1, fmaf(y1, y1, z1 * z1));
        g_dpA[j] = make_ulonglong2(packf2(-2.f * x0, -2.f * x1),
                                   packf2(-2.f * y0, -2.f * y1));
        g_dpB[j] = make_ulonglong2(packf2(-2.f * z0, -2.f * z1),
                                   packf2(w0, w1));
        g_dp4[2 * j + 0] = make_float4(x0, y0, z0, 0.f);
        g_dp4[2 * j + 1] = make_float4(x1, y1, z1, 0.f);
    }
}

// prepB: kNN source column array.
__global__ void prepB_kernel(const float* __restrict__ src) {
    int j = blockIdx.x * 256 + threadIdx.x;   // 0 .. 16383
    const float* p = src + (size_t)j * 3;
    float x = p[0], y = p[1], z = p[2];
    g_cols_src[j] = make_float4(-2.f * x, -2.f * y, -2.f * z,
                                fmaf(x, x, fmaf(y, y, z * z)));
}

// ---------------------------------------------------------------------------
// pd (sum sq diff), sp (sum abs), tran (tiny) — partial sums per block.
__global__ void small_kernel(const float* __restrict__ pw,
                             const float* __restrict__ drp,
                             const float* __restrict__ dpt,
                             const float* __restrict__ rig) {
    __shared__ float red[256];
    int g = blockIdx.x * 256 + threadIdx.x;
    float spa = 0.f, pda = 0.f;
    for (int i = g; i < TT * TOT; i += 64 * 256) {
        spa += fabsf(pw[i]);
        int b3 = i * 3;
        float a = drp[b3 + 0] - dpt[b3 + 0];
        float c = drp[b3 + 1] - dpt[b3 + 1];
        float e = drp[b3 + 2] - dpt[b3 + 2];
        pda += fmaf(a, a, fmaf(c, c, e * e));
    }
    float s1 = block_reduce_sum<256>(pda, red);
    if (threadIdx.x == 0) g_partial[P_PD + blockIdx.x] = s1;
    float s2 = block_reduce_sum<256>(spa, red);
    if (threadIdx.x == 0) g_partial[P_SP + blockIdx.x] = s2;

    float ta = 0.f;
    if (blockIdx.x == 0 && threadIdx.x < TT * BB * 3) {
        int t = threadIdx.x / 12;
        int rem = threadIdx.x % 12;
        int b = rem / 3, r = rem % 3;
        float v = rig[(((t * BB + b) * 4) + r) * 4 + 3];
        ta = v * v;
    }
    float s3 = block_reduce_sum<256>(ta, red);
    if (blockIdx.x == 0 && threadIdx.x == 0) g_partial[P_TRAN] = s3;
}

// ---------------------------------------------------------------------------
// FUSED kernel: chamfer blocks (fma-pipe heavy) + kNN blocks (alu-pipe heavy)
// interleaved 3:2 per group of 5 so both types co-reside per SM. kNN blocks
// process 2 rows/thread for ILP (two independent ladders + FMA chains).
union FusedSmem {
    struct { ulonglong2 tA[CPAIR]; ulonglong2 tB[CPAIR]; } ch;  // 16KB
    float4 nb_tile[NB_COLS];                                    // 8KB
};

__global__ void __launch_bounds__(256) fused_kernel(const float* __restrict__ dpt,
                                                    const float* __restrict__ tgt) {
    __shared__ FusedSmem sm;
    int tid = threadIdx.x;
    int grp = blockIdx.x / 5;
    int lane5 = blockIdx.x % 5;

    if (lane5 < 3) {
        // ----- chamfer part: cid in [0, 384) -----
        int cid = grp * 3 + lane5;
        int by = cid >> 2;             // 0..95 = p*CCH + cc
        int bx = cid & 3;
        int p = by >> 2;               // ((t*BB + b)*2 + dir)
        int cc = by & 3;
        int dir = p & 1;
        int tb = p >> 1;
        int b = tb & 3;

        const float* rowp;
        const ulonglong2 *cA, *cB;
        if (dir == 0) { rowp = dpt + (size_t)tb * NN * 3; cA = g_tgtA + b * NPAIR;  cB = g_tgtB + b * NPAIR; }
        else          { rowp = tgt + (size_t)b * NN * 3;  cA = g_dpA + tb * NPAIR;  cB = g_dpB + tb * NPAIR; }
        cA += cc * CPAIR;
        cB += cc * CPAIR;

        #pragma unroll
        for (int j = tid; j < CPAIR; j += 256) { sm.ch.tA[j] = cA[j]; sm.ch.tB[j] = cB[j]; }
        __syncthreads();

        int m0 = bx * 1024 + tid;      // rows m0, +256, +512, +768
        unsigned long long X0[4], X1[4], X2[4];
        float rlo[4], rhi[4];
        #pragma unroll
        for (int r = 0; r < 4; ++r) {
            const float* rp = rowp + (size_t)(m0 + r * 256) * 3;
            float a0 = rp[0], a1 = rp[1], a2 = rp[2];
            X0[r] = packf2(a0, a0); X1[r] = packf2(a1, a1); X2[r] = packf2(a2, a2);
            rlo[r] = 3.4e38f; rhi[r] = 3.4e38f;
        }

        #pragma unroll 4
        for (int j = 0; j < CPAIR; ++j) {
            ulonglong2 ca = sm.ch.tA[j];
            ulonglong2 cb = sm.ch.tB[j];
            #pragma unroll
            for (int r = 0; r < 4; ++r) {
                unsigned long long d = fma2(X2[r], cb.x, cb.y);
                d = fma2(X1[r], ca.y, d);
                d = fma2(X0[r], ca.x, d);
                float lo, hi;
                unpackf2(lo, hi, d);
                rlo[r] = fminf(rlo[r], lo);
                rhi[r] = fminf(rhi[r], hi);
            }
        }
        float* out = g_cmin + (size_t)by * NN;
        #pragma unroll
        for (int r = 0; r < 4; ++r)
            out[m0 + r * 256] = fminf(rlo[r], rhi[r]);
    } else {
        // ----- kNN part: nid in [0, 256), 2 rows per thread -----
        int nid = grp * 2 + (lane5 - 3);
        int chunk = nid & 7;
        int rb = nid >> 3;             // 0..31
        int m0 = rb * 512 + tid;       // rows m0 and m0+256 (same batch b)
        int m1 = m0 + 256;
        int b = m0 >> 12;

        const float4* cb = g_cols_src + b * NN + chunk * NB_COLS;
        #pragma unroll
        for (int j = tid; j < NB_COLS; j += 256) sm.nb_tile[j] = cb[j];
        __syncthreads();

        float4 meA = g_cols_src[m0];   // (-2x,-2y,-2z,|x|^2)
        float4 meB = g_cols_src[m1];
        float ax = -0.5f * meA.x, ay = -0.5f * meA.y, az = -0.5f * meA.z, aw = meA.w;
        float bx2 = -0.5f * meB.x, by2 = -0.5f * meB.y, bz2 = -0.5f * meB.z, bw = meB.w;

        unsigned int bdA[NB_K], bdB[NB_K];
        #pragma unroll
        for (int k = 0; k < NB_K; ++k) { bdA[k] = 0x7F800000u; bdB[k] = 0x7F800000u; }

        unsigned int nbase = chunk * NB_COLS;
        #pragma unroll 2
        for (int j = 0; j < NB_COLS; j += 2) {
            float4 q0 = sm.nb_tile[j];
            float4 q1 = sm.nb_tile[j + 1];
            // row A, columns j, j+1
            float dA0 = fmaf(az, q0.z, q0.w);
            float dA1 = fmaf(az, q1.z, q1.w);
            float dB0 = fmaf(bz2, q0.z, q0.w);
            float dB1 = fmaf(bz2, q1.z, q1.w);
            dA0 = fmaf(ay, q0.y, dA0);  dA1 = fmaf(ay, q1.y, dA1);
            dB0 = fmaf(by2, q0.y, dB0); dB1 = fmaf(by2, q1.y, dB1);
            dA0 = fmaf(ax, q0.x, dA0);  dA1 = fmaf(ax, q1.x, dA1);
            dB0 = fmaf(bx2, q0.x, dB0); dB1 = fmaf(bx2, q1.x, dB1);
            dA0 += aw; dA1 += aw;       // true sq distance >= ~0
            dB0 += bw; dB1 += bw;
            unsigned int tA0 = (__float_as_uint(dA0) & 0x7FFFF000u) | (nbase + j);
            unsigned int tA1 = (__float_as_uint(dA1) & 0x7FFFF000u) | (nbase + j + 1);
            unsigned int tB0 = (__float_as_uint(dB0) & 0x7FFFF000u) | (nbase + j);
            unsigned int tB1 = (__float_as_uint(dB1) & 0x7FFFF000u) | (nbase + j + 1);
            merge_pair9(bdA, min(tA0, tA1), max(tA0, tA1));
            merge_pair9(bdB, min(tB0, tB1), max(tB0, tB1));
        }
        #pragma unroll
        for (int k = 0; k < NB_K; ++k) {
            g_nb[(chunk * NB_K + k) * TOT + m0] = bdA[k];
            g_nb[(chunk * NB_K + k) * TOT + m1] = bdB[k];
        }
    }
}

// ---------------------------------------------------------------------------
// Post pass (one kernel, block-type dispatch):
//  blocks [0,64):    kNN merge of 8 sorted top-9 lists -> idx + sd
//  blocks [64,448):  chamfer combine (4 chunk mins + |x|^2 -> partial sums)
__global__ void __launch_bounds__(256) post_kernel(const float* __restrict__ dpt,
                                                   const float* __restrict__ tgt) {
    int tid = threadIdx.x;
    if (blockIdx.x < 64) {
        int m = blockIdx.x * 256 + tid;
        unsigned int bd[NB_K];
        #pragma unroll
        for (int k = 0; k < NB_K; ++k) bd[k] = g_nb[k * TOT + m];
        for (int c = 1; c < NB_CHUNKS; ++c) {
            #pragma unroll
            for (int k = 0; k < NB_K; ++k) {
                unsigned int t = g_nb[(c * NB_K + k) * TOT + m];
                if (t >= bd[NB_K - 1]) break;     // both lists sorted ascending
                #pragma unroll
                for (int s = 0; s < NB_K; ++s) {
                    unsigned int lo = min(bd[s], t);
                    t = max(bd[s], t);
                    bd[s] = lo;
                }
            }
        }
        float4 me = g_cols_src[m];
        float x0 = -0.5f * me.x, x1 = -0.5f * me.y, x2 = -0.5f * me.z;
        int ml = m & (NN - 1);
        int mb = m & ~(NN - 1);                   // b*NN
        int cnt = 0;
        #pragma unroll
        for (int s = 0; s < NB_K; ++s) {
            int j = (int)(bd[s] & 0xFFFu);
            if (j != ml && cnt < KK) {
                float4 q = g_cols_src[mb + j];
                float d = fmaf(x2, q.z, q.w);
                d = fmaf(x1, q.y, d);
                d = fmaf(x0, q.x, d);
                d += me.w;
                g_idx[cnt * TOT + m] = j;
                g_sd[cnt * TOT + m]  = sqrtf(d + 1e-5f);
                cnt++;
            }
        }
    } else {
        __shared__ float red[256];
        int cid = blockIdx.x - 64;            // 0..383
        int p = cid >> 4;                     // 0..23
        int bx = cid & 15;
        int dir = p & 1;
        int tb = p >> 1;
        int b = tb & 3;
        const float* rowp = (dir == 0) ? dpt + (size_t)tb * NN * 3
                                       : tgt + (size_t)b * NN * 3;
        int m = bx * 256 + tid;
        const float* cm = g_cmin + (size_t)p * CCH * NN + m;
        float v = fminf(fminf(cm[0], cm[NN]), fminf(cm[2 * NN], cm[3 * NN]));
        const float* rp = rowp + (size_t)m * 3;
        float x0 = rp[0], x1 = rp[1], x2 = rp[2];
        v += fmaf(x0, x0, fmaf(x1, x1, x2 * x2));
        float s = block_reduce_sum<256>(v, red);
        if (tid == 0) g_partial[P_CH + p * 16 + bx] = s;
    }
}

// ---------------------------------------------------------------------------
// ARAP per t: gather dp neighbors (float4 LDG.128), compare to source dists.
__global__ void arap_kernel() {
    __shared__ float red[256];
    int t = blockIdx.y;
    int i = blockIdx.x * 256 + threadIdx.x;    // b*NN + n
    int b = i >> 12;
    const float4* dpb = g_dp4 + (size_t)(t * BB + b) * NN;
    float4 pme = dpb[i & (NN - 1)];
    float acc = 0.f;
    #pragma unroll
    for (int k = 0; k < KK; ++k) {
        int j = g_idx[k * TOT + i];
        float4 q = dpb[j];
        float dx = q.x - pme.x;
        float dy = q.y - pme.y;
        float dz = q.z - pme.z;
        float dd = sqrtf(fmaf(dx, dx, fmaf(dy, dy, dz * dz)) + 1e-5f);
        float df = dd - g_sd[k * TOT + i];
        acc = fmaf(df, df, acc);
    }
    float s = block_reduce_sum<256>(acc, red);
    if (threadIdx.x == 0) g_partial[P_ARAP + t * 64 + blockIdx.x] = s;
}

// ---------------------------------------------------------------------------
// Final deterministic weighted reduction of all partial slots.
__global__ void final_kernel(float* __restrict__ out) {
    __shared__ float red[256];
    int tid = threadIdx.x;
    float acc = 0.f;
    for (int s = tid; s < NPART; s += 256) {
        float w;
        if (s < P_PD)        w = 0.5f / BB;          // chamfer: *0.5/B
        else if (s < P_SP)   w = 1.0f / BB;          // pd: /B
        else if (s < P_TRAN) w = 1.0f / (BB * NN);   // sp: mean over B*N
        else                 w = 1.0f / BB;          // tran + arap: /B
        acc += w * g_partial[s];
    }
    float s = block_reduce_sum<256>(acc, red);
    if (tid == 0) out[0] = s;
}

// ---------------------------------------------------------------------------
extern "C" void kernel_launch(void* const* d_in, const int* in_sizes, int n_in,
                              void* d_out, int out_size) {
    (void)in_sizes; (void)n_in; (void)out_size;
    const float* pw  = (const float*)d_in[1];  // point_weight [T,B,N,1]
    const float* drp = (const float*)d_in[2];  // deform_rigid_points [T,B,N,3]
    const float* dpt = (const float*)d_in[3];  // deformation_points [T,B,N,3]
    const float* rig = (const float*)d_in[4];  // rigid_matrix [T,B,4,4]
    const float* src = (const float*)d_in[5];  // source_points [B,N,3]
    const float* tgt = (const float*)d_in[6];  // target_points [B,N,3]

    prepA_kernel<<<128, 256>>>(tgt, dpt);
    prepB_kernel<<<64, 256>>>(src);
    small_kernel<<<64, 256>>>(pw, drp, dpt, rig);
    fused_kernel<<<FUSED_BLOCKS, 256>>>(dpt, tgt);   // 4th launch — ncu target
    post_kernel<<<448, 256>>>(dpt, tgt);
    arap_kernel<<<dim3(TOT / 256, TT), 256>>>();
    final_kernel<<<1, 256>>>((float*)d_out);
}

// round 14
// speedup vs baseline: 1.9384x; 1.9384x over previous
#include <cuda_runtime.h>
#include <math.h>

// Shapes fixed by the problem: T=3, B=4, N=4096, K=8.
constexpr int TT = 3;
constexpr int BB = 4;
constexpr int NN = 4096;
constexpr int KK = 8;
constexpr int TOT = BB * NN;               // 16384 rows
constexpr int NB_CHUNKS = 8;
constexpr int NB_COLS = NN / NB_CHUNKS;    // 512
constexpr int NB_K = 9;                    // top-9 (self dropped in merge)
constexpr int NPAIR = NN / 2;              // 2048 packed column pairs per set
constexpr int CCH = 4;                     // chamfer column chunks
constexpr int CPAIR = NPAIR / CCH;         // 512 pairs per chamfer chunk
constexpr int CH_BLOCKS = 24 * CCH * 4;    // 384 chamfer blocks (96 jobs x 4)
constexpr int NB_BLOCKS = 512;             // 64 row-blocks x 8 chunks, 1 row/thread
constexpr int FUSED_BLOCKS = CH_BLOCKS + NB_BLOCKS; // 896 = 128 * 7

// Partial-sum slot layout (deterministic reduction — no float atomics)
constexpr int P_CH   = 0;                  // 24 problems * 16 blocks = 384
constexpr int P_PD   = 384;                // 64
constexpr int P_SP   = 448;                // 64
constexpr int P_TRAN = 512;                // 1
constexpr int P_ARAP = 513;                // 3 * 64 = 192
constexpr int NPART  = 705;

// Scratch (device globals — no allocations allowed)
__device__ ulonglong2 g_tgtA[BB * NPAIR];      // (-2x pair, -2y pair) target
__device__ ulonglong2 g_tgtB[BB * NPAIR];      // (-2z pair, |p|^2 pair)
__device__ ulonglong2 g_dpA[TT * BB * NPAIR];  // same for deformation pts
__device__ ulonglong2 g_dpB[TT * BB * NPAIR];
__device__ float4 g_cols_src[TOT];             // (-2x,-2y,-2z,|x|^2) src (kNN)
__device__ float4 g_dp4[TT * TOT];             // raw dp coords (arap gathers)
__device__ unsigned int g_nb[NB_CHUNKS * NB_K * TOT];  // packed keys [chunk][k][m]
__device__ int    g_idx[KK * TOT];             // [k][m]
__device__ float  g_sd[KK * TOT];
__device__ float  g_cmin[24 * CCH * NN];       // chamfer partial row-mins (true dist)
__device__ float  g_partial[NPART];

// ---------------------------------------------------------------------------
__device__ __forceinline__ unsigned long long packf2(float a, float b) {
    unsigned long long r;
    asm("mov.b64 %0, {%1, %2};" : "=l"(r) : "f"(a), "f"(b));
    return r;
}
__device__ __forceinline__ void unpacku2(unsigned int& a, unsigned int& b,
                                         unsigned long long v) {
    asm("mov.b64 {%0, %1}, %2;" : "=r"(a), "=r"(b) : "l"(v));
}
__device__ __forceinline__ unsigned long long fma2(unsigned long long a,
                                                   unsigned long long b,
                                                   unsigned long long c) {
    unsigned long long d;
    asm("fma.rn.f32x2 %0, %1, %2, %3;" : "=l"(d) : "l"(a), "l"(b), "l"(c));
    return d;
}
__device__ __forceinline__ unsigned long long add2(unsigned long long a,
                                                   unsigned long long b) {
    unsigned long long d;
    asm("add.rn.f32x2 %0, %1, %2;" : "=l"(d) : "l"(a), "l"(b));
    return d;
}

template <int BS>
__device__ __forceinline__ float block_reduce_sum(float v, float* sh) {
    int tid = threadIdx.x;
    sh[tid] = v;
    __syncthreads();
    #pragma unroll
    for (int s = BS / 2; s > 0; s >>= 1) {
        if (tid < s) sh[tid] += sh[tid + s];
        __syncthreads();
    }
    float r = sh[0];
    __syncthreads();
    return r;
}

// Merge a sorted key pair (lo <= hi) into the sorted top-9 bd[] via DPX
// vimin3; evaluated descending so old slot values are consumed first.
__device__ __forceinline__ void merge_pair9(unsigned int (&bd)[NB_K],
                                            unsigned int lo, unsigned int hi) {
    #pragma unroll
    for (int s = NB_K - 1; s >= 2; --s)
        bd[s] = __vimin3_u32(bd[s], max(bd[s - 1], lo), max(bd[s - 2], hi));
    bd[1] = __vimin3_u32(bd[1], max(bd[0], lo), hi);
    bd[0] = min(bd[0], lo);
}

// ---------------------------------------------------------------------------
// prepA: packed f32x2 chamfer columns for target + dp, and raw dp4 coords.
__global__ void prepA_kernel(const float* __restrict__ tgt,
                             const float* __restrict__ dpt) {
    int i = blockIdx.x * 256 + threadIdx.x;   // 0 .. 32767
    if (i < BB * NPAIR) {                     // target pairs
        const float* p = tgt + (size_t)i * 6;
        float x0 = p[0], y0 = p[1], z0 = p[2];
        float x1 = p[3], y1 = p[4], z1 = p[5];
        float w0 = fmaf(x0, x0, fmaf(y0, y0, z0 * z0));
        float w1 = fmaf(x1, x1, fmaf(y1, y1, z1 * z1));
        g_tgtA[i] = make_ulonglong2(packf2(-2.f * x0, -2.f * x1),
                                    packf2(-2.f * y0, -2.f * y1));
        g_tgtB[i] = make_ulonglong2(packf2(-2.f * z0, -2.f * z1),
                                    packf2(w0, w1));
    } else {                                  // dp pairs (+ raw dp4)
        int j = i - BB * NPAIR;
        if (j >= TT * BB * NPAIR) return;
        const float* p = dpt + (size_t)j * 6;
        float x0 = p[0], y0 = p[1], z0 = p[2];
        float x1 = p[3], y1 = p[4], z1 = p[5];
        float w0 = fmaf(x0, x0, fmaf(y0, y0, z0 * z0));
        float w1 = fmaf(x1, x1, fmaf(y1, y1, z1 * z1));
        g_dpA[j] = make_ulonglong2(packf2(-2.f * x0, -2.f * x1),
                                   packf2(-2.f * y0, -2.f * y1));
        g_dpB[j] = make_ulonglong2(packf2(-2.f * z0, -2.f * z1),
                                   packf2(w0, w1));
        g_dp4[2 * j + 0] = make_float4(x0, y0, z0, 0.f);
        g_dp4[2 * j + 1] = make_float4(x1, y1, z1, 0.f);
    }
}

// prepB: kNN source column array.
__global__ void prepB_kernel(const float* __restrict__ src) {
    int j = blockIdx.x * 256 + threadIdx.x;   // 0 .. 16383
    const float* p = src + (size_t)j * 3;
    float x = p[0], y = p[1], z = p[2];
    g_cols_src[j] = make_float4(-2.f * x, -2.f * y, -2.f * z,
                                fmaf(x, x, fmaf(y, y, z * z)));
}

// ---------------------------------------------------------------------------
// pd (sum sq diff), sp (sum abs), tran (tiny) — partial sums per block.
__global__ void small_kernel(const float* __restrict__ pw,
                             const float* __restrict__ drp,
                             const float* __restrict__ dpt,
                             const float* __restrict__ rig) {
    __shared__ float red[256];
    int g = blockIdx.x * 256 + threadIdx.x;
    float spa = 0.f, pda = 0.f;
    for (int i = g; i < TT * TOT; i += 64 * 256) {
        spa += fabsf(pw[i]);
        int b3 = i * 3;
        float a = drp[b3 + 0] - dpt[b3 + 0];
        float c = drp[b3 + 1] - dpt[b3 + 1];
        float e = drp[b3 + 2] - dpt[b3 + 2];
        pda += fmaf(a, a, fmaf(c, c, e * e));
    }
    float s1 = block_reduce_sum<256>(pda, red);
    if (threadIdx.x == 0) g_partial[P_PD + blockIdx.x] = s1;
    float s2 = block_reduce_sum<256>(spa, red);
    if (threadIdx.x == 0) g_partial[P_SP + blockIdx.x] = s2;

    float ta = 0.f;
    if (blockIdx.x == 0 && threadIdx.x < TT * BB * 3) {
        int t = threadIdx.x / 12;
        int rem = threadIdx.x % 12;
        int b = rem / 3, r = rem % 3;
        float v = rig[(((t * BB + b) * 4) + r) * 4 + 3];
        ta = v * v;
    }
    float s3 = block_reduce_sum<256>(ta, red);
    if (blockIdx.x == 0 && threadIdx.x == 0) g_partial[P_TRAN] = s3;
}

// ---------------------------------------------------------------------------
// FUSED kernel: chamfer blocks (fma-pipe heavy) + kNN blocks (alu-pipe heavy)
// interleaved 3:4 per group of 7 so both types co-reside per SM.
// Chamfer: |x|^2 folded into the f32x2 accumulator so distances are true
// (>=0) values; running min kept as float BITS via one vimin3 per 2 cols per
// row (replaces 2 FMNMX — halves chamfer's alu-pipe load).
union FusedSmem {
    struct { ulonglong2 tA[CPAIR]; ulonglong2 tB[CPAIR]; } ch;  // 16KB
    float4 nb_tile[NB_COLS];                                    // 8KB
};

__global__ void __launch_bounds__(256) fused_kernel(const float* __restrict__ dpt,
                                                    const float* __restrict__ tgt) {
    __shared__ FusedSmem sm;
    int tid = threadIdx.x;
    int grp = blockIdx.x / 7;
    int lane7 = blockIdx.x % 7;

    if (lane7 < 3) {
        // ----- chamfer part: cid in [0, 384) -----
        int cid = grp * 3 + lane7;
        int by = cid >> 2;             // 0..95 = p*CCH + cc
        int bx = cid & 3;
        int p = by >> 2;               // ((t*BB + b)*2 + dir)
        int cc = by & 3;
        int dir = p & 1;
        int tb = p >> 1;
        int b = tb & 3;

        const float* rowp;
        const ulonglong2 *cA, *cB;
        if (dir == 0) { rowp = dpt + (size_t)tb * NN * 3; cA = g_tgtA + b * NPAIR;  cB = g_tgtB + b * NPAIR; }
        else          { rowp = tgt + (size_t)b * NN * 3;  cA = g_dpA + tb * NPAIR;  cB = g_dpB + tb * NPAIR; }
        cA += cc * CPAIR;
        cB += cc * CPAIR;

        #pragma unroll
        for (int j = tid; j < CPAIR; j += 256) { sm.ch.tA[j] = cA[j]; sm.ch.tB[j] = cB[j]; }
        __syncthreads();

        int m0 = bx * 1024 + tid;      // rows m0, +256, +512, +768
        unsigned long long X0[4], X1[4], X2[4], W2[4];
        unsigned int rmin[4];
        #pragma unroll
        for (int r = 0; r < 4; ++r) {
            const float* rp = rowp + (size_t)(m0 + r * 256) * 3;
            float a0 = rp[0], a1 = rp[1], a2 = rp[2];
            float w = fmaf(a0, a0, fmaf(a1, a1, a2 * a2));
            X0[r] = packf2(a0, a0); X1[r] = packf2(a1, a1); X2[r] = packf2(a2, a2);
            W2[r] = packf2(w, w);
            rmin[r] = 0x7F800000u;     // +inf bits
        }

        #pragma unroll 4
        for (int j = 0; j < CPAIR; ++j) {
            ulonglong2 ca = sm.ch.tA[j];
            ulonglong2 cb = sm.ch.tB[j];
            #pragma unroll
            for (int r = 0; r < 4; ++r) {
                unsigned long long d = fma2(X2[r], cb.x, add2(cb.y, W2[r]));
                d = fma2(X1[r], ca.y, d);
                d = fma2(X0[r], ca.x, d);
                unsigned int lo, hi;
                unpacku2(lo, hi, d);   // free register aliasing
                rmin[r] = __vimin3_u32(rmin[r], lo, hi);  // bits monotone (d>=0)
            }
        }
        float* out = g_cmin + (size_t)by * NN;
        #pragma unroll
        for (int r = 0; r < 4; ++r)
            out[m0 + r * 256] = __uint_as_float(rmin[r]);   // true min distance
    } else {
        // ----- kNN part: nid in [0, 512), 1 row per thread (proven shape) -----
        int nid = grp * 4 + (lane7 - 3);
        int chunk = nid & 7;
        int rb = nid >> 3;
        int m = rb * 256 + tid;        // 0 .. TOT-1
        int b = m >> 12;

        const float4* cb = g_cols_src + b * NN + chunk * NB_COLS;
        #pragma unroll
        for (int j = tid; j < NB_COLS; j += 256) sm.nb_tile[j] = cb[j];
        __syncthreads();

        float4 me = g_cols_src[m];     // (-2x,-2y,-2z,|x|^2)
        float x0 = -0.5f * me.x, x1 = -0.5f * me.y, x2 = -0.5f * me.z;
        float x2m = me.w;

        unsigned int bd[NB_K];
        #pragma unroll
        for (int k = 0; k < NB_K; ++k) bd[k] = 0x7F800000u;   // +inf keys

        unsigned int nbase = chunk * NB_COLS;
        #pragma unroll 4
        for (int j = 0; j < NB_COLS; j += 2) {
            float4 q0 = sm.nb_tile[j];
            float4 q1 = sm.nb_tile[j + 1];
            float d0 = fmaf(x2, q0.z, q0.w);
            float d1 = fmaf(x2, q1.z, q1.w);
            d0 = fmaf(x1, q0.y, d0);
            d1 = fmaf(x1, q1.y, d1);
            d0 = fmaf(x0, q0.x, d0);
            d1 = fmaf(x0, q1.x, d1);
            d0 += x2m;                                    // true sq dist >= ~0
            d1 += x2m;
            unsigned int t0 = (__float_as_uint(d0) & 0x7FFFF000u) | (nbase + j);
            unsigned int t1 = (__float_as_uint(d1) & 0x7FFFF000u) | (nbase + j + 1);
            merge_pair9(bd, min(t0, t1), max(t0, t1));
        }
        #pragma unroll
        for (int k = 0; k < NB_K; ++k)
            g_nb[(chunk * NB_K + k) * TOT + m] = bd[k];
    }
}

// ---------------------------------------------------------------------------
// Post pass (one kernel, block-type dispatch):
//  blocks [0,64):    kNN merge of 8 sorted top-9 lists -> idx + sd
//  blocks [64,448):  chamfer combine (min of 4 chunk true-distance mins)
__global__ void __launch_bounds__(256) post_kernel() {
    int tid = threadIdx.x;
    if (blockIdx.x < 64) {
        int m = blockIdx.x * 256 + tid;
        unsigned int bd[NB_K];
        #pragma unroll
        for (int k = 0; k < NB_K; ++k) bd[k] = g_nb[k * TOT + m];
        for (int c = 1; c < NB_CHUNKS; ++c) {
            #pragma unroll
            for (int k = 0; k < NB_K; ++k) {
                unsigned int t = g_nb[(c * NB_K + k) * TOT + m];
                if (t >= bd[NB_K - 1]) break;     // both lists sorted ascending
                #pragma unroll
                for (int s = 0; s < NB_K; ++s) {
                    unsigned int lo = min(bd[s], t);
                    t = max(bd[s], t);
                    bd[s] = lo;
                }
            }
        }
        float4 me = g_cols_src[m];
        float x0 = -0.5f * me.x, x1 = -0.5f * me.y, x2 = -0.5f * me.z;
        int ml = m & (NN - 1);
        int mb = m & ~(NN - 1);                   // b*NN
        int cnt = 0;
        #pragma unroll
        for (int s = 0; s < NB_K; ++s) {
            int j = (int)(bd[s] & 0xFFFu);
            if (j != ml && cnt < KK) {
                float4 q = g_cols_src[mb + j];
                float d = fmaf(x2, q.z, q.w);
                d = fmaf(x1, q.y, d);
                d = fmaf(x0, q.x, d);
                d += me.w;
                g_idx[cnt * TOT + m] = j;
                g_sd[cnt * TOT + m]  = sqrtf(d + 1e-5f);
                cnt++;
            }
        }
    } else {
        __shared__ float red[256];
        int cid = blockIdx.x - 64;            // 0..383
        int p = cid >> 4;                     // 0..23
        int bx = cid & 15;
        int m = bx * 256 + tid;
        const float* cm = g_cmin + (size_t)p * CCH * NN + m;
        float v = fminf(fminf(cm[0], cm[NN]), fminf(cm[2 * NN], cm[3 * NN]));
        float s = block_reduce_sum<256>(v, red);
        if (tid == 0) g_partial[P_CH + p * 16 + bx] = s;
    }
}

// ---------------------------------------------------------------------------
// ARAP per t: gather dp neighbors (float4 LDG.128), compare to source dists.
__global__ void arap_kernel() {
    __shared__ float red[256];
    int t = blockIdx.y;
    int i = blockIdx.x * 256 + threadIdx.x;    // b*NN + n
    int b = i >> 12;
    const float4* dpb = g_dp4 + (size_t)(t * BB + b) * NN;
    float4 pme = dpb[i & (NN - 1)];
    float acc = 0.f;
    #pragma unroll
    for (int k = 0; k < KK; ++k) {
        int j = g_idx[k * TOT + i];
        float4 q = dpb[j];
        float dx = q.x - pme.x;
        float dy = q.y - pme.y;
        float dz = q.z - pme.z;
        float dd = sqrtf(fmaf(dx, dx, fmaf(dy, dy, dz * dz)) + 1e-5f);
        float df = dd - g_sd[k * TOT + i];
        acc = fmaf(df, df, acc);
    }
    float s = block_reduce_sum<256>(acc, red);
    if (threadIdx.x == 0) g_partial[P_ARAP + t * 64 + blockIdx.x] = s;
}

// ---------------------------------------------------------------------------
// Final deterministic weighted reduction of all partial slots.
__global__ void final_kernel(float* __restrict__ out) {
    __shared__ float red[256];
    int tid = threadIdx.x;
    float acc = 0.f;
    for (int s = tid; s < NPART; s += 256) {
        float w;
        if (s < P_PD)        w = 0.5f / BB;          // chamfer: *0.5/B
        else if (s < P_SP)   w = 1.0f / BB;          // pd: /B
        else if (s < P_TRAN) w = 1.0f / (BB * NN);   // sp: mean over B*N
        else                 w = 1.0f / BB;          // tran + arap: /B
        acc += w * g_partial[s];
    }
    float s = block_reduce_sum<256>(acc, red);
    if (tid == 0) out[0] = s;
}

// ---------------------------------------------------------------------------
extern "C" void kernel_launch(void* const* d_in, const int* in_sizes, int n_in,
                              void* d_out, int out_size) {
    (void)in_sizes; (void)n_in; (void)out_size;
    const float* pw  = (const float*)d_in[1];  // point_weight [T,B,N,1]
    const float* drp = (const float*)d_in[2];  // deform_rigid_points [T,B,N,3]
    const float* dpt = (const float*)d_in[3];  // deformation_points [T,B,N,3]
    const float* rig = (const float*)d_in[4];  // rigid_matrix [T,B,4,4]
    const float* src = (const float*)d_in[5];  // source_points [B,N,3]
    const float* tgt = (const float*)d_in[6];  // target_points [B,N,3]

    prepA_kernel<<<128, 256>>>(tgt, dpt);
    prepB_kernel<<<64, 256>>>(src);
    small_kernel<<<64, 256>>>(pw, drp, dpt, rig);
    fused_kernel<<<FUSED_BLOCKS, 256>>>(dpt, tgt);   // 4th launch — ncu target
    post_kernel<<<448, 256>>>();
    arap_kernel<<<dim3(TOT / 256, TT), 256>>>();
    final_kernel<<<1, 256>>>((float*)d_out);
}

// round 15
// speedup vs baseline: 2.1529x; 1.1106x over previous
#include <cuda_runtime.h>
#include <math.h>

// Shapes fixed by the problem: T=3, B=4, N=4096, K=8.
constexpr int TT = 3;
constexpr int BB = 4;
constexpr int NN = 4096;
constexpr int KK = 8;
constexpr int TOT = BB * NN;               // 16384 rows
constexpr int NB_CHUNKS = 8;
constexpr int NB_COLS = NN / NB_CHUNKS;    // 512
constexpr int NB_K = 9;                    // top-9 (self dropped in merge)
constexpr int NPAIR = NN / 2;              // 2048 packed column pairs per set
constexpr int CCH = 4;                     // chamfer column chunks
constexpr int CPAIR = NPAIR / CCH;         // 512 pairs per chamfer chunk
constexpr int CH_BLOCKS = 24 * CCH * 4;    // 384 chamfer blocks (96 jobs x 4)
constexpr int NB_BLOCKS = 512;             // 64 row-blocks x 8 chunks, 1 row/thread
constexpr int FUSED_BLOCKS = CH_BLOCKS + NB_BLOCKS; // 896 = 128 * 7

constexpr float CBIAS = 16.0f;             // chamfer positivity bias (>= max |x|^2)

// Partial-sum slot layout (deterministic reduction — no float atomics)
constexpr int P_CH   = 0;                  // 24 problems * 16 blocks = 384
constexpr int P_PD   = 384;                // 64
constexpr int P_SP   = 448;                // 64
constexpr int P_TRAN = 512;                // 1
constexpr int P_ARAP = 513;                // 3 * 64 = 192
constexpr int NPART  = 705;

// Scratch (device globals — no allocations allowed)
__device__ ulonglong2 g_tgtA[BB * NPAIR];      // (-2x pair, -2y pair) target
__device__ ulonglong2 g_tgtB[BB * NPAIR];      // (-2z pair, |p|^2+C pair)
__device__ ulonglong2 g_dpA[TT * BB * NPAIR];  // same for deformation pts
__device__ ulonglong2 g_dpB[TT * BB * NPAIR];
__device__ float4 g_cols_src[TOT];             // (-2x,-2y,-2z,|x|^2) src (kNN, unbiased)
__device__ float4 g_dp4[TT * TOT];             // raw dp coords (arap gathers)
__device__ unsigned int g_nb[NB_CHUNKS * NB_K * TOT];  // packed keys [chunk][k][m]
__device__ float  g_cmin[24 * CCH * NN];       // chamfer partial row-mins (biased dist)
__device__ float  g_partial[NPART];

// ---------------------------------------------------------------------------
__device__ __forceinline__ unsigned long long packf2(float a, float b) {
    unsigned long long r;
    asm("mov.b64 %0, {%1, %2};" : "=l"(r) : "f"(a), "f"(b));
    return r;
}
__device__ __forceinline__ void unpacku2(unsigned int& a, unsigned int& b,
                                         unsigned long long v) {
    asm("mov.b64 {%0, %1}, %2;" : "=r"(a), "=r"(b) : "l"(v));
}
__device__ __forceinline__ unsigned long long fma2(unsigned long long a,
                                                   unsigned long long b,
                                                   unsigned long long c) {
    unsigned long long d;
    asm("fma.rn.f32x2 %0, %1, %2, %3;" : "=l"(d) : "l"(a), "l"(b), "l"(c));
    return d;
}

template <int BS>
__device__ __forceinline__ float block_reduce_sum(float v, float* sh) {
    int tid = threadIdx.x;
    sh[tid] = v;
    __syncthreads();
    #pragma unroll
    for (int s = BS / 2; s > 0; s >>= 1) {
        if (tid < s) sh[tid] += sh[tid + s];
        __syncthreads();
    }
    float r = sh[0];
    __syncthreads();
    return r;
}

// Merge a sorted key pair (lo <= hi) into the sorted top-9 bd[] via DPX
// vimin3; evaluated descending so old slot values are consumed first.
__device__ __forceinline__ void merge_pair9(unsigned int (&bd)[NB_K],
                                            unsigned int lo, unsigned int hi) {
    #pragma unroll
    for (int s = NB_K - 1; s >= 2; --s)
        bd[s] = __vimin3_u32(bd[s], max(bd[s - 1], lo), max(bd[s - 2], hi));
    bd[1] = __vimin3_u32(bd[1], max(bd[0], lo), hi);
    bd[0] = min(bd[0], lo);
}

// ---------------------------------------------------------------------------
// Combined prep + small: blocks [0,128) chamfer column packing (tgt+dp, with
// +CBIAS), [128,192) kNN source columns (unbiased), [192,256) pd/sp/tran sums.
__global__ void __launch_bounds__(256) prep_kernel(const float* __restrict__ tgt,
                                                   const float* __restrict__ dpt,
                                                   const float* __restrict__ src,
                                                   const float* __restrict__ pw,
                                                   const float* __restrict__ drp,
                                                   const float* __restrict__ rig) {
    int bx = blockIdx.x;
    int tid = threadIdx.x;
    if (bx < 128) {
        int i = bx * 256 + tid;                   // 0 .. 32767
        if (i < BB * NPAIR) {                     // target pairs
            const float* p = tgt + (size_t)i * 6;
            float x0 = p[0], y0 = p[1], z0 = p[2];
            float x1 = p[3], y1 = p[4], z1 = p[5];
            float w0 = fmaf(x0, x0, fmaf(y0, y0, z0 * z0)) + CBIAS;
            float w1 = fmaf(x1, x1, fmaf(y1, y1, z1 * z1)) + CBIAS;
            g_tgtA[i] = make_ulonglong2(packf2(-2.f * x0, -2.f * x1),
                                        packf2(-2.f * y0, -2.f * y1));
            g_tgtB[i] = make_ulonglong2(packf2(-2.f * z0, -2.f * z1),
                                        packf2(w0, w1));
        } else {                                  // dp pairs (+ raw dp4)
            int j = i - BB * NPAIR;
            const float* p = dpt + (size_t)j * 6;
            float x0 = p[0], y0 = p[1], z0 = p[2];
            float x1 = p[3], y1 = p[4], z1 = p[5];
            float w0 = fmaf(x0, x0, fmaf(y0, y0, z0 * z0)) + CBIAS;
            float w1 = fmaf(x1, x1, fmaf(y1, y1, z1 * z1)) + CBIAS;
            g_dpA[j] = make_ulonglong2(packf2(-2.f * x0, -2.f * x1),
                                       packf2(-2.f * y0, -2.f * y1));
            g_dpB[j] = make_ulonglong2(packf2(-2.f * z0, -2.f * z1),
                                       packf2(w0, w1));
            g_dp4[2 * j + 0] = make_float4(x0, y0, z0, 0.f);
            g_dp4[2 * j + 1] = make_float4(x1, y1, z1, 0.f);
        }
    } else if (bx < 192) {
        int j = (bx - 128) * 256 + tid;           // 0 .. 16383
        const float* p = src + (size_t)j * 3;
        float x = p[0], y = p[1], z = p[2];
        g_cols_src[j] = make_float4(-2.f * x, -2.f * y, -2.f * z,
                                    fmaf(x, x, fmaf(y, y, z * z)));
    } else {
        __shared__ float red[256];
        int sb = bx - 192;                        // 0..63
        int g = sb * 256 + tid;
        float spa = 0.f, pda = 0.f;
        for (int i = g; i < TT * TOT; i += 64 * 256) {
            spa += fabsf(pw[i]);
            int b3 = i * 3;
            float a = drp[b3 + 0] - dpt[b3 + 0];
            float c = drp[b3 + 1] - dpt[b3 + 1];
            float e = drp[b3 + 2] - dpt[b3 + 2];
            pda += fmaf(a, a, fmaf(c, c, e * e));
        }
        float s1 = block_reduce_sum<256>(pda, red);
        if (tid == 0) g_partial[P_PD + sb] = s1;
        float s2 = block_reduce_sum<256>(spa, red);
        if (tid == 0) g_partial[P_SP + sb] = s2;

        float ta = 0.f;
        if (sb == 0 && tid < TT * BB * 3) {
            int t = tid / 12;
            int rem = tid % 12;
            int b = rem / 3, r = rem % 3;
            float v = rig[(((t * BB + b) * 4) + r) * 4 + 3];
            ta = v * v;
        }
        float s3 = block_reduce_sum<256>(ta, red);
        if (sb == 0 && tid == 0) g_partial[P_TRAN] = s3;
    }
}

// ---------------------------------------------------------------------------
// FUSED kernel: chamfer blocks (fma-pipe heavy) + kNN blocks (alu-pipe heavy)
// interleaved 3:4 per group of 7. Chamfer: CBIAS pre-folded into column w so
// distances are strictly positive — bits monotone, min = one vimin3; the
// inner loop is exactly 3 FFMA2 + 1 VIMNMX3 per 2 cols per row.
union FusedSmem {
    struct { ulonglong2 tA[CPAIR]; ulonglong2 tB[CPAIR]; } ch;  // 16KB
    float4 nb_tile[NB_COLS];                                    // 8KB
};

__global__ void __launch_bounds__(256) fused_kernel(const float* __restrict__ dpt,
                                                    const float* __restrict__ tgt) {
    __shared__ FusedSmem sm;
    int tid = threadIdx.x;
    int grp = blockIdx.x / 7;
    int lane7 = blockIdx.x % 7;

    if (lane7 < 3) {
        // ----- chamfer part: cid in [0, 384) -----
        int cid = grp * 3 + lane7;
        int by = cid >> 2;             // 0..95 = p*CCH + cc
        int bx = cid & 3;
        int p = by >> 2;               // ((t*BB + b)*2 + dir)
        int cc = by & 3;
        int dir = p & 1;
        int tb = p >> 1;
        int b = tb & 3;

        const float* rowp;
        const ulonglong2 *cA, *cB;
        if (dir == 0) { rowp = dpt + (size_t)tb * NN * 3; cA = g_tgtA + b * NPAIR;  cB = g_tgtB + b * NPAIR; }
        else          { rowp = tgt + (size_t)b * NN * 3;  cA = g_dpA + tb * NPAIR;  cB = g_dpB + tb * NPAIR; }
        cA += cc * CPAIR;
        cB += cc * CPAIR;

        #pragma unroll
        for (int j = tid; j < CPAIR; j += 256) { sm.ch.tA[j] = cA[j]; sm.ch.tB[j] = cB[j]; }
        __syncthreads();

        int m0 = bx * 1024 + tid;      // rows m0, +256, +512, +768
        unsigned long long X0[4], X1[4], X2[4];
        unsigned int rmin[4];
        #pragma unroll
        for (int r = 0; r < 4; ++r) {
            const float* rp = rowp + (size_t)(m0 + r * 256) * 3;
            float a0 = rp[0], a1 = rp[1], a2 = rp[2];
            X0[r] = packf2(a0, a0); X1[r] = packf2(a1, a1); X2[r] = packf2(a2, a2);
            rmin[r] = 0x7F800000u;     // +inf bits
        }

        #pragma unroll 4
        for (int j = 0; j < CPAIR; ++j) {
            ulonglong2 ca = sm.ch.tA[j];
            ulonglong2 cb = sm.ch.tB[j];
            #pragma unroll
            for (int r = 0; r < 4; ++r) {
                unsigned long long d = fma2(X2[r], cb.x, cb.y);  // w has +CBIAS
                d = fma2(X1[r], ca.y, d);
                d = fma2(X0[r], ca.x, d);
                unsigned int lo, hi;
                unpacku2(lo, hi, d);   // free register aliasing
                rmin[r] = __vimin3_u32(rmin[r], lo, hi);  // bits monotone (d>0)
            }
        }
        float* out = g_cmin + (size_t)by * NN;
        #pragma unroll
        for (int r = 0; r < 4; ++r)
            out[m0 + r * 256] = __uint_as_float(rmin[r]);   // biased min distance
    } else {
        // ----- kNN part: nid in [0, 512), 1 row per thread (proven shape) -----
        int nid = grp * 4 + (lane7 - 3);
        int chunk = nid & 7;
        int rb = nid >> 3;
        int m = rb * 256 + tid;        // 0 .. TOT-1
        int b = m >> 12;

        const float4* cb = g_cols_src + b * NN + chunk * NB_COLS;
        #pragma unroll
        for (int j = tid; j < NB_COLS; j += 256) sm.nb_tile[j] = cb[j];
        __syncthreads();

        float4 me = g_cols_src[m];     // (-2x,-2y,-2z,|x|^2)
        float x0 = -0.5f * me.x, x1 = -0.5f * me.y, x2 = -0.5f * me.z;
        float x2m = me.w;

        unsigned int bd[NB_K];
        #pragma unroll
        for (int k = 0; k < NB_K; ++k) bd[k] = 0x7F800000u;   // +inf keys

        unsigned int nbase = chunk * NB_COLS;
        #pragma unroll 4
        for (int j = 0; j < NB_COLS; j += 2) {
            float4 q0 = sm.nb_tile[j];
            float4 q1 = sm.nb_tile[j + 1];
            float d0 = fmaf(x2, q0.z, q0.w);
            float d1 = fmaf(x2, q1.z, q1.w);
            d0 = fmaf(x1, q0.y, d0);
            d1 = fmaf(x1, q1.y, d1);
            d0 = fmaf(x0, q0.x, d0);
            d1 = fmaf(x0, q1.x, d1);
            d0 += x2m;                                    // true sq dist >= ~0
            d1 += x2m;
            unsigned int t0 = (__float_as_uint(d0) & 0x7FFFF000u) | (nbase + j);
            unsigned int t1 = (__float_as_uint(d1) & 0x7FFFF000u) | (nbase + j + 1);
            merge_pair9(bd, min(t0, t1), max(t0, t1));
        }
        #pragma unroll
        for (int k = 0; k < NB_K; ++k)
            g_nb[(chunk * NB_K + k) * TOT + m] = bd[k];
    }
}

// ---------------------------------------------------------------------------
// Post pass (one kernel, block-type dispatch):
//  blocks [0,64):    kNN merge of 8 sorted top-9 lists -> idx/sd in registers,
//                    then ARAP for all 3 t's inline (idx/sd never hit memory)
//  blocks [64,448):  chamfer combine (min of 4 biased mins, -C + |x|^2)
__global__ void __launch_bounds__(256) post_kernel(const float* __restrict__ dpt,
                                                   const float* __restrict__ tgt) {
    __shared__ float red[256];
    int tid = threadIdx.x;
    if (blockIdx.x < 64) {
        int m = blockIdx.x * 256 + tid;
        unsigned int bd[NB_K];
        #pragma unroll
        for (int k = 0; k < NB_K; ++k) bd[k] = g_nb[k * TOT + m];
        for (int c = 1; c < NB_CHUNKS; ++c) {
            #pragma unroll
            for (int k = 0; k < NB_K; ++k) {
                unsigned int t = g_nb[(c * NB_K + k) * TOT + m];
                if (t >= bd[NB_K - 1]) break;     // both lists sorted ascending
                #pragma unroll
                for (int s = 0; s < NB_K; ++s) {
                    unsigned int lo = min(bd[s], t);
                    t = max(bd[s], t);
                    bd[s] = lo;
                }
            }
        }
        float4 me = g_cols_src[m];
        float x0 = -0.5f * me.x, x1 = -0.5f * me.y, x2 = -0.5f * me.z;
        int ml = m & (NN - 1);
        int mb = m & ~(NN - 1);                   // b*NN
        int nidx[KK];
        float nsd[KK];
        int cnt = 0;
        #pragma unroll
        for (int s = 0; s < NB_K; ++s) {
            int j = (int)(bd[s] & 0xFFFu);
            if (j != ml && cnt < KK) {
                float4 q = g_cols_src[mb + j];
                float d = fmaf(x2, q.z, q.w);
                d = fmaf(x1, q.y, d);
                d = fmaf(x0, q.x, d);
                d += me.w;
                nidx[cnt] = j;
                nsd[cnt]  = sqrtf(d + 1e-5f);
                cnt++;
            }
        }
        // ARAP inline for each t (always cnt == 8: 9 distinct idx, <=1 self)
        #pragma unroll
        for (int t = 0; t < TT; ++t) {
            const float4* dpb = g_dp4 + (size_t)t * TOT + mb;
            float4 pme = dpb[ml];
            float acc = 0.f;
            #pragma unroll
            for (int k = 0; k < KK; ++k) {
                float4 q = dpb[nidx[k]];
                float dx = q.x - pme.x;
                float dy = q.y - pme.y;
                float dz = q.z - pme.z;
                float dd = sqrtf(fmaf(dx, dx, fmaf(dy, dy, dz * dz)) + 1e-5f);
                float df = dd - nsd[k];
                acc = fmaf(df, df, acc);
            }
            float s = block_reduce_sum<256>(acc, red);
            if (tid == 0) g_partial[P_ARAP + t * 64 + blockIdx.x] = s;
        }
    } else {
        int cid = blockIdx.x - 64;            // 0..383
        int p = cid >> 4;                     // 0..23
        int bx = cid & 15;
        int dir = p & 1;
        int tb = p >> 1;
        int b = tb & 3;
        const float* rowp = (dir == 0) ? dpt + (size_t)tb * NN * 3
                                       : tgt + (size_t)b * NN * 3;
        int m = bx * 256 + tid;
        const float* cm = g_cmin + (size_t)p * CCH * NN + m;
        float v = fminf(fminf(cm[0], cm[NN]), fminf(cm[2 * NN], cm[3 * NN]));
        const float* rp = rowp + (size_t)m * 3;
        float x0 = rp[0], x1 = rp[1], x2 = rp[2];
        v += fmaf(x0, x0, fmaf(x1, x1, x2 * x2)) - CBIAS;   // undo bias, add |x|^2
        float s = block_reduce_sum<256>(v, red);
        if (tid == 0) g_partial[P_CH + p * 16 + bx] = s;
    }
}

// ---------------------------------------------------------------------------
// Final deterministic weighted reduction of all partial slots.
__global__ void final_kernel(float* __restrict__ out) {
    __shared__ float red[256];
    int tid = threadIdx.x;
    float acc = 0.f;
    for (int s = tid; s < NPART; s += 256) {
        float w;
        if (s < P_PD)        w = 0.5f / BB;          // chamfer: *0.5/B
        else if (s < P_SP)   w = 1.0f / BB;          // pd: /B
        else if (s < P_TRAN) w = 1.0f / (BB * NN);   // sp: mean over B*N
        else                 w = 1.0f / BB;          // tran + arap: /B
        acc += w * g_partial[s];
    }
    float s = block_reduce_sum<256>(acc, red);
    if (tid == 0) out[0] = s;
}

// ---------------------------------------------------------------------------
extern "C" void kernel_launch(void* const* d_in, const int* in_sizes, int n_in,
                              void* d_out, int out_size) {
    (void)in_sizes; (void)n_in; (void)out_size;
    const float* pw  = (const float*)d_in[1];  // point_weight [T,B,N,1]
    const float* drp = (const float*)d_in[2];  // deform_rigid_points [T,B,N,3]
    const float* dpt = (const float*)d_in[3];  // deformation_points [T,B,N,3]
    const float* rig = (const float*)d_in[4];  // rigid_matrix [T,B,4,4]
    const float* src = (const float*)d_in[5];  // source_points [B,N,3]
    const float* tgt = (const float*)d_in[6];  // target_points [B,N,3]

    prep_kernel<<<256, 256>>>(tgt, dpt, src, pw, drp, rig);
    fused_kernel<<<FUSED_BLOCKS, 256>>>(dpt, tgt);   // launch idx 1 (5 = replay 2)
    post_kernel<<<448, 256>>>(dpt, tgt);
    final_kernel<<<1, 256>>>((float*)d_out);
}

// round 16
// speedup vs baseline: 2.1696x; 1.0078x over previous
#include <cuda_runtime.h>
#include <math.h>

// Shapes fixed by the problem: T=3, B=4, N=4096, K=8.
constexpr int TT = 3;
constexpr int BB = 4;
constexpr int NN = 4096;
constexpr int KK = 8;
constexpr int TOT = BB * NN;               // 16384 rows
constexpr int NB_CHUNKS = 8;
constexpr int NB_COLS = NN / NB_CHUNKS;    // 512
constexpr int NB_K = 9;                    // top-9 (self dropped in merge)
constexpr int NPAIR = NN / 2;              // 2048 packed column pairs per set
constexpr int CCH = 4;                     // chamfer column chunks
constexpr int CPAIR = NPAIR / CCH;         // 512 pairs per chamfer chunk
constexpr int CH_ITEMS = 24 * CCH * 4;     // 384 chamfer work items
constexpr int NB_ITEMS = 512;              // kNN work items
constexpr int FUSED_BLOCKS = 448;          // one wave; each block runs 2 items

constexpr float CBIAS = 16.0f;             // chamfer positivity bias (>= max |x|^2)

// Partial-sum slot layout (deterministic reduction — no float atomics)
constexpr int P_CH   = 0;                  // 24 problems * 16 blocks = 384
constexpr int P_PD   = 384;                // 64
constexpr int P_SP   = 448;                // 64
constexpr int P_TRAN = 512;                // 1
constexpr int P_ARAP = 513;                // 3 * 64 = 192
constexpr int NPART  = 705;
constexpr int POST_BLOCKS = 448;

// Scratch (device globals — no allocations allowed)
__device__ ulonglong2 g_tgtA[BB * NPAIR];      // (-2x pair, -2y pair) target
__device__ ulonglong2 g_tgtB[BB * NPAIR];      // (-2z pair, |p|^2+C pair)
__device__ ulonglong2 g_dpA[TT * BB * NPAIR];  // same for deformation pts
__device__ ulonglong2 g_dpB[TT * BB * NPAIR];
__device__ float4 g_cols_src[TOT];             // (-2x,-2y,-2z,|x|^2) src (kNN)
__device__ float4 g_dp4[TT * TOT];             // raw dp coords (arap gathers)
__device__ unsigned int g_nb[NB_CHUNKS * NB_K * TOT];  // packed keys [chunk][k][m]
__device__ float  g_cmin[24 * CCH * NN];       // chamfer partial row-mins (biased)
__device__ float  g_partial[NPART];
__device__ int    g_cnt;                       // post-kernel completion counter

// ---------------------------------------------------------------------------
__device__ __forceinline__ unsigned long long packf2(float a, float b) {
    unsigned long long r;
    asm("mov.b64 %0, {%1, %2};" : "=l"(r) : "f"(a), "f"(b));
    return r;
}
__device__ __forceinline__ void unpacku2(unsigned int& a, unsigned int& b,
                                         unsigned long long v) {
    asm("mov.b64 {%0, %1}, %2;" : "=r"(a), "=r"(b) : "l"(v));
}
__device__ __forceinline__ unsigned long long fma2(unsigned long long a,
                                                   unsigned long long b,
                                                   unsigned long long c) {
    unsigned long long d;
    asm("fma.rn.f32x2 %0, %1, %2, %3;" : "=l"(d) : "l"(a), "l"(b), "l"(c));
    return d;
}

template <int BS>
__device__ __forceinline__ float block_reduce_sum(float v, float* sh) {
    int tid = threadIdx.x;
    sh[tid] = v;
    __syncthreads();
    #pragma unroll
    for (int s = BS / 2; s > 0; s >>= 1) {
        if (tid < s) sh[tid] += sh[tid + s];
        __syncthreads();
    }
    float r = sh[0];
    __syncthreads();
    return r;
}

// Merge a sorted key pair (lo <= hi) into the sorted top-9 bd[] via DPX
// vimin3; evaluated descending so old slot values are consumed first.
__device__ __forceinline__ void merge_pair9(unsigned int (&bd)[NB_K],
                                            unsigned int lo, unsigned int hi) {
    #pragma unroll
    for (int s = NB_K - 1; s >= 2; --s)
        bd[s] = __vimin3_u32(bd[s], max(bd[s - 1], lo), max(bd[s - 2], hi));
    bd[1] = __vimin3_u32(bd[1], max(bd[0], lo), hi);
    bd[0] = min(bd[0], lo);
}

// ---------------------------------------------------------------------------
// Combined prep + small: blocks [0,128) chamfer column packing (tgt+dp, with
// +CBIAS), [128,192) kNN source columns (unbiased), [192,256) pd/sp/tran sums.
__global__ void __launch_bounds__(256) prep_kernel(const float* __restrict__ tgt,
                                                   const float* __restrict__ dpt,
                                                   const float* __restrict__ src,
                                                   const float* __restrict__ pw,
                                                   const float* __restrict__ drp,
                                                   const float* __restrict__ rig) {
    int bx = blockIdx.x;
    int tid = threadIdx.x;
    if (bx == 0 && tid == 0) g_cnt = 0;          // reset post completion counter
    if (bx < 128) {
        int i = bx * 256 + tid;                   // 0 .. 32767
        if (i < BB * NPAIR) {                     // target pairs
            const float* p = tgt + (size_t)i * 6;
            float x0 = p[0], y0 = p[1], z0 = p[2];
            float x1 = p[3], y1 = p[4], z1 = p[5];
            float w0 = fmaf(x0, x0, fmaf(y0, y0, z0 * z0)) + CBIAS;
            float w1 = fmaf(x1, x1, fmaf(y1, y1, z1 * z1)) + CBIAS;
            g_tgtA[i] = make_ulonglong2(packf2(-2.f * x0, -2.f * x1),
                                        packf2(-2.f * y0, -2.f * y1));
            g_tgtB[i] = make_ulonglong2(packf2(-2.f * z0, -2.f * z1),
                                        packf2(w0, w1));
        } else {                                  // dp pairs (+ raw dp4)
            int j = i - BB * NPAIR;
            const float* p = dpt + (size_t)j * 6;
            float x0 = p[0], y0 = p[1], z0 = p[2];
            float x1 = p[3], y1 = p[4], z1 = p[5];
            float w0 = fmaf(x0, x0, fmaf(y0, y0, z0 * z0)) + CBIAS;
            float w1 = fmaf(x1, x1, fmaf(y1, y1, z1 * z1)) + CBIAS;
            g_dpA[j] = make_ulonglong2(packf2(-2.f * x0, -2.f * x1),
                                       packf2(-2.f * y0, -2.f * y1));
            g_dpB[j] = make_ulonglong2(packf2(-2.f * z0, -2.f * z1),
                                       packf2(w0, w1));
            g_dp4[2 * j + 0] = make_float4(x0, y0, z0, 0.f);
            g_dp4[2 * j + 1] = make_float4(x1, y1, z1, 0.f);
        }
    } else if (bx < 192) {
        int j = (bx - 128) * 256 + tid;           // 0 .. 16383
        const float* p = src + (size_t)j * 3;
        float x = p[0], y = p[1], z = p[2];
        g_cols_src[j] = make_float4(-2.f * x, -2.f * y, -2.f * z,
                                    fmaf(x, x, fmaf(y, y, z * z)));
    } else {
        __shared__ float red[256];
        int sb = bx - 192;                        // 0..63
        int g = sb * 256 + tid;
        float spa = 0.f, pda = 0.f;
        for (int i = g; i < TT * TOT; i += 64 * 256) {
            spa += fabsf(pw[i]);
            int b3 = i * 3;
            float a = drp[b3 + 0] - dpt[b3 + 0];
            float c = drp[b3 + 1] - dpt[b3 + 1];
            float e = drp[b3 + 2] - dpt[b3 + 2];
            pda += fmaf(a, a, fmaf(c, c, e * e));
        }
        float s1 = block_reduce_sum<256>(pda, red);
        if (tid == 0) g_partial[P_PD + sb] = s1;
        float s2 = block_reduce_sum<256>(spa, red);
        if (tid == 0) g_partial[P_SP + sb] = s2;

        float ta = 0.f;
        if (sb == 0 && tid < TT * BB * 3) {
            int t = tid / 12;
            int rem = tid % 12;
            int b = rem / 3, r = rem % 3;
            float v = rig[(((t * BB + b) * 4) + r) * 4 + 3];
            ta = v * v;
        }
        float s3 = block_reduce_sum<256>(ta, red);
        if (sb == 0 && tid == 0) g_partial[P_TRAN] = s3;
    }
}

// ---------------------------------------------------------------------------
// FUSED kernel, single-wave: 448 blocks x 2 work items (item b and b+448).
// Items 0..383 = chamfer (fma heavy), 384..895 = kNN (alu heavy); most blocks
// run one of each, parity-alternated order to stagger pipe phases per SM.
union FusedSmem {
    struct { ulonglong2 tA[CPAIR]; ulonglong2 tB[CPAIR]; } ch;  // 16KB
    float4 nb_tile[NB_COLS];                                    // 8KB
};

__device__ __forceinline__ void do_chamfer(FusedSmem& sm, int cid, int tid,
                                           const float* __restrict__ dpt,
                                           const float* __restrict__ tgt) {
    int by = cid >> 2;             // 0..95 = p*CCH + cc
    int bx = cid & 3;
    int p = by >> 2;               // ((t*BB + b)*2 + dir)
    int cc = by & 3;
    int dir = p & 1;
    int tb = p >> 1;
    int b = tb & 3;

    const float* rowp;
    const ulonglong2 *cA, *cB;
    if (dir == 0) { rowp = dpt + (size_t)tb * NN * 3; cA = g_tgtA + b * NPAIR;  cB = g_tgtB + b * NPAIR; }
    else          { rowp = tgt + (size_t)b * NN * 3;  cA = g_dpA + tb * NPAIR;  cB = g_dpB + tb * NPAIR; }
    cA += cc * CPAIR;
    cB += cc * CPAIR;

    #pragma unroll
    for (int j = tid; j < CPAIR; j += 256) { sm.ch.tA[j] = cA[j]; sm.ch.tB[j] = cB[j]; }
    __syncthreads();

    int m0 = bx * 1024 + tid;      // rows m0, +256, +512, +768
    unsigned long long X0[4], X1[4], X2[4];
    unsigned int rmin[4];
    #pragma unroll
    for (int r = 0; r < 4; ++r) {
        const float* rp = rowp + (size_t)(m0 + r * 256) * 3;
        float a0 = rp[0], a1 = rp[1], a2 = rp[2];
        X0[r] = packf2(a0, a0); X1[r] = packf2(a1, a1); X2[r] = packf2(a2, a2);
        rmin[r] = 0x7F800000u;     // +inf bits
    }

    #pragma unroll 4
    for (int j = 0; j < CPAIR; ++j) {
        ulonglong2 ca = sm.ch.tA[j];
        ulonglong2 cb = sm.ch.tB[j];
        #pragma unroll
        for (int r = 0; r < 4; ++r) {
            unsigned long long d = fma2(X2[r], cb.x, cb.y);  // w has +CBIAS
            d = fma2(X1[r], ca.y, d);
            d = fma2(X0[r], ca.x, d);
            unsigned int lo, hi;
            unpacku2(lo, hi, d);   // free register aliasing
            rmin[r] = __vimin3_u32(rmin[r], lo, hi);  // bits monotone (d>0)
        }
    }
    float* out = g_cmin + (size_t)by * NN;
    #pragma unroll
    for (int r = 0; r < 4; ++r)
        out[m0 + r * 256] = __uint_as_float(rmin[r]);   // biased min distance
}

__device__ __forceinline__ void do_nb(FusedSmem& sm, int nid, int tid) {
    int chunk = nid & 7;
    int rb = nid >> 3;
    int m = rb * 256 + tid;        // 0 .. TOT-1
    int b = m >> 12;

    const float4* cb = g_cols_src + b * NN + chunk * NB_COLS;
    #pragma unroll
    for (int j = tid; j < NB_COLS; j += 256) sm.nb_tile[j] = cb[j];
    __syncthreads();

    float4 me = g_cols_src[m];     // (-2x,-2y,-2z,|x|^2)
    float x0 = -0.5f * me.x, x1 = -0.5f * me.y, x2 = -0.5f * me.z;
    float x2m = me.w;

    unsigned int bd[NB_K];
    #pragma unroll
    for (int k = 0; k < NB_K; ++k) bd[k] = 0x7F800000u;   // +inf keys

    unsigned int nbase = chunk * NB_COLS;
    #pragma unroll 4
    for (int j = 0; j < NB_COLS; j += 2) {
        float4 q0 = sm.nb_tile[j];
        float4 q1 = sm.nb_tile[j + 1];
        float d0 = fmaf(x2, q0.z, q0.w);
        float d1 = fmaf(x2, q1.z, q1.w);
        d0 = fmaf(x1, q0.y, d0);
        d1 = fmaf(x1, q1.y, d1);
        d0 = fmaf(x0, q0.x, d0);
        d1 = fmaf(x0, q1.x, d1);
        d0 += x2m;                                    // true sq dist >= ~0
        d1 += x2m;
        unsigned int t0 = (__float_as_uint(d0) & 0x7FFFF000u) | (nbase + j);
        unsigned int t1 = (__float_as_uint(d1) & 0x7FFFF000u) | (nbase + j + 1);
        merge_pair9(bd, min(t0, t1), max(t0, t1));
    }
    #pragma unroll
    for (int k = 0; k < NB_K; ++k)
        g_nb[(chunk * NB_K + k) * TOT + m] = bd[k];
}

__device__ __forceinline__ void do_item(FusedSmem& sm, int idx, int tid,
                                        const float* __restrict__ dpt,
                                        const float* __restrict__ tgt) {
    if (idx < CH_ITEMS) do_chamfer(sm, idx, tid, dpt, tgt);
    else                do_nb(sm, idx - CH_ITEMS, tid);
}

__global__ void __launch_bounds__(256) fused_kernel(const float* __restrict__ dpt,
                                                    const float* __restrict__ tgt) {
    __shared__ FusedSmem sm;
    int tid = threadIdx.x;
    int b = blockIdx.x;
    int iA = b, iB = b + FUSED_BLOCKS;
    if (b & 1) { int t = iA; iA = iB; iB = t; }   // stagger phases across SM
    do_item(sm, iA, tid, dpt, tgt);
    __syncthreads();                               // all smem readers done
    do_item(sm, iB, tid, dpt, tgt);
}

// ---------------------------------------------------------------------------
// Post pass (one kernel, block-type dispatch):
//  blocks [0,64):    kNN merge of 8 sorted top-9 lists -> idx/sd in registers,
//                    then ARAP for all 3 t's inline (idx/sd never hit memory)
//  blocks [64,448):  chamfer combine (min of 4 biased mins, -C + |x|^2)
// Last block to finish performs the final weighted reduction (deterministic:
// fixed slots read in fixed order).
__global__ void __launch_bounds__(256) post_kernel(const float* __restrict__ dpt,
                                                   const float* __restrict__ tgt,
                                                   float* __restrict__ out) {
    __shared__ float red[256];
    __shared__ int is_last;
    int tid = threadIdx.x;
    if (blockIdx.x < 64) {
        int m = blockIdx.x * 256 + tid;
        unsigned int bd[NB_K];
        #pragma unroll
        for (int k = 0; k < NB_K; ++k) bd[k] = g_nb[k * TOT + m];
        for (int c = 1; c < NB_CHUNKS; ++c) {
            #pragma unroll
            for (int k = 0; k < NB_K; ++k) {
                unsigned int t = g_nb[(c * NB_K + k) * TOT + m];
                if (t >= bd[NB_K - 1]) break;     // both lists sorted ascending
                #pragma unroll
                for (int s = 0; s < NB_K; ++s) {
                    unsigned int lo = min(bd[s], t);
                    t = max(bd[s], t);
                    bd[s] = lo;
                }
            }
        }
        float4 me = g_cols_src[m];
        float x0 = -0.5f * me.x, x1 = -0.5f * me.y, x2 = -0.5f * me.z;
        int ml = m & (NN - 1);
        int mb = m & ~(NN - 1);                   // b*NN
        int nidx[KK];
        float nsd[KK];
        int cnt = 0;
        #pragma unroll
        for (int s = 0; s < NB_K; ++s) {
            int j = (int)(bd[s] & 0xFFFu);
            if (j != ml && cnt < KK) {
                float4 q = g_cols_src[mb + j];
                float d = fmaf(x2, q.z, q.w);
                d = fmaf(x1, q.y, d);
                d = fmaf(x0, q.x, d);
                d += me.w;
                nidx[cnt] = j;
                nsd[cnt]  = sqrtf(d + 1e-5f);
                cnt++;
            }
        }
        // ARAP inline for each t (always cnt == 8: 9 distinct idx, <=1 self)
        #pragma unroll
        for (int t = 0; t < TT; ++t) {
            const float4* dpb = g_dp4 + (size_t)t * TOT + mb;
            float4 pme = dpb[ml];
            float acc = 0.f;
            #pragma unroll
            for (int k = 0; k < KK; ++k) {
                float4 q = dpb[nidx[k]];
                float dx = q.x - pme.x;
                float dy = q.y - pme.y;
                float dz = q.z - pme.z;
                float dd = sqrtf(fmaf(dx, dx, fmaf(dy, dy, dz * dz)) + 1e-5f);
                float df = dd - nsd[k];
                acc = fmaf(df, df, acc);
            }
            float s = block_reduce_sum<256>(acc, red);
            if (tid == 0) g_partial[P_ARAP + t * 64 + blockIdx.x] = s;
        }
    } else {
        int cid = blockIdx.x - 64;            // 0..383
        int p = cid >> 4;                     // 0..23
        int bx = cid & 15;
        int dir = p & 1;
        int tb = p >> 1;
        int b = tb & 3;
        const float* rowp = (dir == 0) ? dpt + (size_t)tb * NN * 3
                                       : tgt + (size_t)b * NN * 3;
        int m = bx * 256 + tid;
        const float* cm = g_cmin + (size_t)p * CCH * NN + m;
        float v = fminf(fminf(cm[0], cm[NN]), fminf(cm[2 * NN], cm[3 * NN]));
        const float* rp = rowp + (size_t)m * 3;
        float x0 = rp[0], x1 = rp[1], x2 = rp[2];
        v += fmaf(x0, x0, fmaf(x1, x1, x2 * x2)) - CBIAS;   // undo bias, add |x|^2
        float s = block_reduce_sum<256>(v, red);
        if (tid == 0) g_partial[P_CH + p * 16 + bx] = s;
    }

    // ---- last-block final reduction (deterministic fixed-order sum) ----
    __syncthreads();
    if (tid == 0) {
        __threadfence();
        is_last = (atomicAdd(&g_cnt, 1) == POST_BLOCKS - 1);
    }
    __syncthreads();
    if (is_last) {
        __threadfence();                       // acquire all partials
        float acc = 0.f;
        for (int s = tid; s < NPART; s += 256) {
            float w;
            if (s < P_PD)        w = 0.5f / BB;          // chamfer: *0.5/B
            else if (s < P_SP)   w = 1.0f / BB;          // pd: /B
            else if (s < P_TRAN) w = 1.0f / (BB * NN);   // sp: mean over B*N
            else                 w = 1.0f / BB;          // tran + arap: /B
            acc += w * g_partial[s];
        }
        float s = block_reduce_sum<256>(acc, red);
        if (tid == 0) out[0] = s;
    }
}

// ---------------------------------------------------------------------------
extern "C" void kernel_launch(void* const* d_in, const int* in_sizes, int n_in,
                              void* d_out, int out_size) {
    (void)in_sizes; (void)n_in; (void)out_size;
    const float* pw  = (const float*)d_in[1];  // point_weight [T,B,N,1]
    const float* drp = (const float*)d_in[2];  // deform_rigid_points [T,B,N,3]
    const float* dpt = (const float*)d_in[3];  // deformation_points [T,B,N,3]
    const float* rig = (const float*)d_in[4];  // rigid_matrix [T,B,4,4]
    const float* src = (const float*)d_in[5];  // source_points [B,N,3]
    const float* tgt = (const float*)d_in[6];  // target_points [B,N,3]

    prep_kernel<<<256, 256>>>(tgt, dpt, src, pw, drp, rig);
    fused_kernel<<<FUSED_BLOCKS, 256>>>(dpt, tgt);   // single wave, 2 items/block
    post_kernel<<<POST_BLOCKS, 256>>>(dpt, tgt, (float*)d_out);
}